// round 12
// baseline (speedup 1.0000x reference)
#include <cuda_runtime.h>
#include <cuda_bf16.h>
#include <math.h>
#include <stdint.h>

#define B_ 4096
#define D_ 512
#define P_ 256
#define C_ 8
#define ESCALE 64.0f
#define EINV   (1.0f / 64.0f)

// ---------------- scratch (device globals; no allocation allowed) ----------
__device__ __align__(128) float g_tp[P_ * D_];   // tp[p,i] = omega[c_p] @ w[p]
__device__ __align__(128) float g_u[P_ * D_];    // u[p,j]  = omega[c_p]^T @ tp[p]
__device__ float g_p2[P_];                       // ||tp_p||^2
__device__ __align__(128) float g_x2p[4][C_][B_]; // x2 correction partials
__device__ __align__(128) float g_xsq[B_];       // ||x_b||^2 (fp32 exact)
__device__ float g_sg[B_ / 32];                  // per-dist-CTA sigmoid sums
__device__ float g_norm[512];                    // norm partials
__device__ __align__(128) __nv_bfloat16 g_xb[B_ * D_];  // X bf16 (dist A operand)
__device__ __align__(128) uint8_t g_xe[B_ * D_];        // X e4m3 (x2 A operand)
__device__ __align__(128) uint8_t g_ome[C_ * D_ * D_];  // E=omega-I scaled e4m3
__device__ __align__(128) __nv_bfloat16 g_ub[P_ * D_];  // u bf16

// ======================= helpers ===========================================
__device__ __forceinline__ uint32_t smem_u32(const void* p) {
    uint32_t a;
    asm("{ .reg .u64 t; cvta.to.shared.u64 t, %1; cvt.u32.u64 %0, t; }"
        : "=r"(a) : "l"(p));
    return a;
}

#define CP_ASYNC16(dst, src) \
    asm volatile("cp.async.cg.shared.global [%0], [%1], 16;" \
                 :: "r"(dst), "l"(src) : "memory")
#define CP_COMMIT() asm volatile("cp.async.commit_group;" ::: "memory")
#define CP_WAIT(n)  asm volatile("cp.async.wait_group %0;" :: "n"(n) : "memory")

// SW128-style swizzle (rows are 128 bytes)
#define SW(b) ((b) ^ (((b) >> 3) & 0x70))

#define MMA_BF16(d, a, b) \
    asm volatile("mma.sync.aligned.m16n8k16.row.col.f32.bf16.bf16.f32 " \
        "{%0,%1,%2,%3}, {%4,%5,%6,%7}, {%8,%9}, {%0,%1,%2,%3};" \
        : "+f"((d)[0]), "+f"((d)[1]), "+f"((d)[2]), "+f"((d)[3]) \
        : "r"((a)[0]), "r"((a)[1]), "r"((a)[2]), "r"((a)[3]), \
          "r"((b)[0]), "r"((b)[1]))

#define MMA_FP8(d, a, b) \
    asm volatile("mma.sync.aligned.m16n8k32.row.col.f32.e4m3.e4m3.f32 " \
        "{%0,%1,%2,%3}, {%4,%5,%6,%7}, {%8,%9}, {%0,%1,%2,%3};" \
        : "+f"((d)[0]), "+f"((d)[1]), "+f"((d)[2]), "+f"((d)[3]) \
        : "r"((a)[0]), "r"((a)[1]), "r"((a)[2]), "r"((a)[3]), \
          "r"((b)[0]), "r"((b)[1]))

#define LDSM_X4(r, addr) \
    asm volatile("ldmatrix.sync.aligned.m8n8.x4.shared.b16 {%0,%1,%2,%3}, [%4];" \
        : "=r"((r)[0]), "=r"((r)[1]), "=r"((r)[2]), "=r"((r)[3]) : "r"(addr))

__device__ __forceinline__ uint32_t pack_e4m3x4(float4 v) {
    uint16_t lo, hi;
    asm("cvt.rn.satfinite.e4m3x2.f32 %0, %1, %2;" : "=h"(lo) : "f"(v.y), "f"(v.x));
    asm("cvt.rn.satfinite.e4m3x2.f32 %0, %1, %2;" : "=h"(hi) : "f"(v.w), "f"(v.z));
    return (uint32_t)lo | ((uint32_t)hi << 16);
}

// ===========================================================================
// side-stream zero of tp/u accumulators
__global__ void zero_side_kernel() {
    int i = blockIdx.x * blockDim.x + threadIdx.x;
    if (i < P_ * D_) { g_tp[i] = 0.0f; g_u[i] = 0.0f; }
}

// X convert: warp per row -> bf16 + e4m3 + exact fp32 rowwise sumsq
__global__ __launch_bounds__(256) void convx_kernel(const float* __restrict__ x) {
    int row = blockIdx.x * 8 + (threadIdx.x >> 5);
    int lane = threadIdx.x & 31;
    const float4* src = (const float4*)(x + (size_t)row * D_);
    float ss = 0.f;
    #pragma unroll
    for (int it = 0; it < 4; it++) {
        int c4 = it * 32 + lane;
        float4 v = src[c4];
        ss += v.x * v.x + v.y * v.y + v.z * v.z + v.w * v.w;
        __nv_bfloat162 lo = __floats2bfloat162_rn(v.x, v.y);
        __nv_bfloat162 hi = __floats2bfloat162_rn(v.z, v.w);
        uint2 o = {*(uint32_t*)&lo, *(uint32_t*)&hi};
        ((uint2*)g_xb)[(size_t)row * 128 + c4] = o;
        ((uint32_t*)g_xe)[(size_t)row * 128 + c4] = pack_e4m3x4(v);
    }
    #pragma unroll
    for (int off = 16; off; off >>= 1) ss += __shfl_xor_sync(0xffffffffu, ss, off);
    if (lane == 0) g_xsq[row] = ss;
}

// E convert: (omega - I) * ESCALE -> e4m3
__global__ __launch_bounds__(256) void conve_kernel(const float* __restrict__ om) {
    int idx4 = blockIdx.x * blockDim.x + threadIdx.x;   // float4 index
    if (idx4 >= C_ * D_ * D_ / 4) return;
    int j0 = (idx4 & 127) * 4;
    int i  = (idx4 >> 7) & 511;
    float4 v = ((const float4*)om)[idx4];
    v.x = (v.x - (float)(j0 + 0 == i)) * ESCALE;
    v.y = (v.y - (float)(j0 + 1 == i)) * ESCALE;
    v.z = (v.z - (float)(j0 + 2 == i)) * ESCALE;
    v.w = (v.w - (float)(j0 + 3 == i)) * ESCALE;
    ((uint32_t*)g_ome)[idx4] = pack_e4m3x4(v);
}

__global__ __launch_bounds__(256) void f2bf_kernel(const float* __restrict__ s,
                                                   __nv_bfloat16* __restrict__ d,
                                                   int n4) {
    int i = blockIdx.x * blockDim.x + threadIdx.x;
    if (i < n4) {
        float4 v = ((const float4*)s)[i];
        __nv_bfloat162 lo = __floats2bfloat162_rn(v.x, v.y);
        __nv_bfloat162 hi = __floats2bfloat162_rn(v.z, v.w);
        uint2 o = {*(uint32_t*)&lo, *(uint32_t*)&hi};
        ((uint2*)d)[i] = o;
    }
}

// tp[p,i] = sum_j omega[c,i,j] * w[p,j]; split-K x4 via atomicAdd
__global__ __launch_bounds__(256) void tp_kernel(const float* __restrict__ omega,
                                                 const float* __restrict__ protos) {
    int c = blockIdx.y;
    int i0 = blockIdx.x * 32;
    int ks = blockIdx.z;
    int tid = threadIdx.x;
    int tx = tid & 31;
    int ty = tid >> 5;
    __shared__ float w_s[32][33];
    __shared__ float om_s[32][33];
    float acc[4] = {0.f, 0.f, 0.f, 0.f};
    for (int t = 0; t < 4; t++) {
        int j0 = ks * 128 + t * 32;
        #pragma unroll
        for (int l = 0; l < 4; l++) {
            int s = tid + l * 256;
            int r = s >> 5, jj = s & 31;
            w_s[r][jj]  = protos[(r * 8 + c) * D_ + j0 + jj];
            om_s[r][jj] = omega[((size_t)c * D_ + i0 + r) * D_ + j0 + jj];
        }
        __syncthreads();
        #pragma unroll
        for (int jj = 0; jj < 32; jj++) {
            float wv = w_s[tx][jj];
            #pragma unroll
            for (int r = 0; r < 4; r++)
                acc[r] += om_s[ty * 4 + r][jj] * wv;
        }
        __syncthreads();
    }
    #pragma unroll
    for (int r = 0; r < 4; r++)
        atomicAdd(&g_tp[(tx * 8 + c) * D_ + i0 + ty * 4 + r], acc[r]);
}

// u[p,j] = sum_i tp[p,i] * omega[c,i,j]; split-K x4 via atomicAdd
__global__ __launch_bounds__(256) void u_kernel(const float* __restrict__ omega) {
    int c = blockIdx.y, j0 = blockIdx.x * 32;
    int ks = blockIdx.z;
    int tid = threadIdx.x;
    int jx = tid & 7;
    int py = tid >> 3;
    __shared__ float tp_s[32][33];
    __shared__ float om_s[32][32];
    float ax = 0.f, ay = 0.f, az = 0.f, aw = 0.f;
    for (int t = 0; t < 4; t++) {
        int i0 = ks * 128 + t * 32;
        #pragma unroll
        for (int l = 0; l < 4; l++) {
            int s = tid + l * 256;
            int p = s >> 5, ii = s & 31;
            tp_s[p][ii] = g_tp[(p * 8 + c) * D_ + i0 + ii];
        }
        #pragma unroll
        for (int l = 0; l < 4; l++) {
            int s = tid + l * 256;
            int ii = s >> 5, jj = s & 31;
            om_s[ii][jj] = omega[((size_t)c * D_ + i0 + ii) * D_ + j0 + jj];
        }
        __syncthreads();
        #pragma unroll
        for (int ii = 0; ii < 32; ii++) {
            float tv = tp_s[py][ii];
            float4 ov = *(const float4*)&om_s[ii][jx * 4];
            ax += tv * ov.x; ay += tv * ov.y; az += tv * ov.z; aw += tv * ov.w;
        }
        __syncthreads();
    }
    float* dst = &g_u[(size_t)(py * 8 + c) * D_ + j0 + jx * 4];
    atomicAdd(dst + 0, ax);
    atomicAdd(dst + 1, ay);
    atomicAdd(dst + 2, az);
    atomicAdd(dst + 3, aw);
}

__global__ void p2_kernel() {
    int p = blockIdx.x;
    int tid = threadIdx.x;
    float s = 0.f;
    for (int i = tid; i < D_; i += 128) {
        float v = g_tp[p * D_ + i];
        s += v * v;
    }
    #pragma unroll
    for (int off = 16; off; off >>= 1) s += __shfl_xor_sync(0xffffffffu, s, off);
    __shared__ float ws[4];
    if ((tid & 31) == 0) ws[tid >> 5] = s;
    __syncthreads();
    if (tid == 0) g_p2[p] = ws[0] + ws[1] + ws[2] + ws[3];
}

// ========== x2 correction via mma.sync e4m3 m16n8k32 + ldmatrix ===========
// Z = X_fp8 @ E_fp8^T; epilogue accumulates z^2 + 2*x*z (fp32 x from input).
// CTA 128m x 128n, K=512 fp8 elems (BK=128 bytes), 4 iters, 3-stage pipeline.
__global__ __launch_bounds__(256) void x2_mma_kernel(const float* __restrict__ xf) {
    extern __shared__ char sm[];
    __shared__ float red[4][128];   // [warp_n][local row]
    const int tid = threadIdx.x, lane = tid & 31, wid = tid >> 5;
    const int warp_m = wid & 1, warp_n = wid >> 1;
    const int b0 = blockIdx.x * 128, ny = blockIdx.y, c = blockIdx.z;
    const int n0 = ny * 128;
    const int r4 = lane >> 2, kq4 = lane & 3;

    const uint8_t* Asrc = g_xe + (size_t)b0 * D_;
    const uint8_t* Bsrc = g_ome + (size_t)c * D_ * D_ + (size_t)n0 * D_;
    uint32_t smB = smem_u32(sm);

    float acc[4][4][4];
    #pragma unroll
    for (int i = 0; i < 4; i++)
        #pragma unroll
        for (int j = 0; j < 4; j++)
            #pragma unroll
            for (int q = 0; q < 4; q++) acc[i][j][q] = 0.f;

    uint32_t aBase[4], aX[4];
    const int aRowL = lane & 15, aHalf = (lane >> 4) * 16;
    #pragma unroll
    for (int mt = 0; mt < 4; mt++) {
        int r = warp_m * 64 + mt * 16 + aRowL;
        aBase[mt] = r * 128; aX[mt] = (r & 7) << 4;
    }
    uint32_t bBase[2], bX[2];
    const int bRowL = ((lane >> 4) << 3) | (lane & 7);
    const int bHalf = ((lane >> 3) & 1) * 16;
    #pragma unroll
    for (int np = 0; np < 2; np++) {
        int r = warp_n * 32 + np * 16 + bRowL;
        bBase[np] = 16384 + r * 128; bX[np] = (r & 7) << 4;
    }

    // stage = 32KB: A 128x128B + B 128x128B (fp8)
    auto load_stage = [&](int buf, int k0) {
        uint32_t aB = smB + buf * 32768;
        uint32_t bB = aB + 16384;
        #pragma unroll
        for (int l = 0; l < 4; l++) {
            int idx = tid + l * 256;
            int m = idx >> 3, kq = idx & 7;
            uint32_t byteo = m * 128 + kq * 16;
            CP_ASYNC16(aB + SW(byteo), Asrc + (size_t)m * D_ + k0 + kq * 16);
        }
        #pragma unroll
        for (int l = 0; l < 4; l++) {
            int idx = tid + l * 256;
            int n = idx >> 3, kq = idx & 7;
            uint32_t byteo = n * 128 + kq * 16;
            CP_ASYNC16(bB + SW(byteo), Bsrc + (size_t)n * D_ + k0 + kq * 16);
        }
        CP_COMMIT();
    };

    load_stage(0, 0);
    load_stage(1, 128);
    for (int it = 0; it < 4; it++) {
        if (it == 3) CP_WAIT(0); else CP_WAIT(1);
        __syncthreads();
        if (it + 2 < 4) load_stage((it + 2) % 3, (it + 2) * 128);
        uint32_t stage = smB + (uint32_t)(it % 3) * 32768;
        #pragma unroll
        for (int ks = 0; ks < 4; ks++) {
            uint32_t kb = ks * 32;   // 32 bytes = k32 fp8 per step
            uint32_t a[4][4], b[2][4];
            #pragma unroll
            for (int mt = 0; mt < 4; mt++)
                LDSM_X4(a[mt], stage + aBase[mt] + ((kb + aHalf) ^ aX[mt]));
            #pragma unroll
            for (int np = 0; np < 2; np++)
                LDSM_X4(b[np], stage + bBase[np] + ((kb + bHalf) ^ bX[np]));
            #pragma unroll
            for (int mt = 0; mt < 4; mt++)
                #pragma unroll
                for (int nt = 0; nt < 4; nt++)
                    MMA_FP8(acc[mt][nt], a[mt], (&b[nt >> 1][(nt & 1) * 2]));
        }
    }

    // epilogue: z = acc/ESCALE; contribution z^2 + 2*x*z, rowwise sum over
    // this CTA's 128 n-cols; cross-warp_n smem reduce; store partial.
    #pragma unroll
    for (int mt = 0; mt < 4; mt++) {
        int r0 = b0 + warp_m * 64 + mt * 16 + r4;
        float s0 = 0.f, s8 = 0.f;
        #pragma unroll
        for (int nt = 0; nt < 4; nt++) {
            int cn = n0 + warp_n * 32 + nt * 8 + kq4 * 2;
            float2 xv0 = *(const float2*)(xf + (size_t)r0 * D_ + cn);
            float2 xv8 = *(const float2*)(xf + (size_t)(r0 + 8) * D_ + cn);
            float z00 = acc[mt][nt][0] * EINV, z01 = acc[mt][nt][1] * EINV;
            float z80 = acc[mt][nt][2] * EINV, z81 = acc[mt][nt][3] * EINV;
            s0 += z00 * (z00 + 2.0f * xv0.x) + z01 * (z01 + 2.0f * xv0.y);
            s8 += z80 * (z80 + 2.0f * xv8.x) + z81 * (z81 + 2.0f * xv8.y);
        }
        s0 += __shfl_xor_sync(0xffffffffu, s0, 1);
        s0 += __shfl_xor_sync(0xffffffffu, s0, 2);
        s8 += __shfl_xor_sync(0xffffffffu, s8, 1);
        s8 += __shfl_xor_sync(0xffffffffu, s8, 2);
        if (kq4 == 0) {
            int rl = warp_m * 64 + mt * 16 + r4;
            red[warp_n][rl]     = s0;
            red[warp_n][rl + 8] = s8;
        }
    }
    __syncthreads();
    if (tid < 128)
        g_x2p[ny][c][b0 + tid] = red[0][tid] + red[1][tid]
                               + red[2][tid] + red[3][tid];
}

// ============== dist via mma.sync bf16 + ldmatrix, fused epilogue ==========
// CTA 32m x 256n x 512 (BK=64), 8 warps (2m x 4n), warp tile 16x64.
__global__ __launch_bounds__(256) void dist_mma_kernel(const int* __restrict__ y,
                                                       const int* __restrict__ labels) {
    extern __shared__ char sm[];
    __shared__ float x2s[C_][32];
    __shared__ float p2_s[P_];
    __shared__ int   lab_s[P_];
    __shared__ int   ys_s[32];
    __shared__ float pos_s[4][32];
    __shared__ float neg_s[4][32];

    const int tid = threadIdx.x, lane = tid & 31, wid = tid >> 5;
    const int warp_m = wid & 1, warp_n = wid >> 1;
    const int b0 = blockIdx.x * 32;
    const int r4 = lane >> 2, kq4 = lane & 3;

    const __nv_bfloat16* Asrc = g_xb + (size_t)b0 * D_;
    uint32_t smB = smem_u32(sm);

    for (int i = tid; i < P_; i += 256) {
        p2_s[i]  = g_p2[i];
        lab_s[i] = labels[i];
    }
    if (tid < C_ * 32) {
        int c = tid >> 5, r = tid & 31;
        x2s[c][r] = g_x2p[0][c][b0 + r] + g_x2p[1][c][b0 + r]
                  + g_x2p[2][c][b0 + r] + g_x2p[3][c][b0 + r]
                  + g_xsq[b0 + r];
    }
    if (tid < 32) ys_s[tid] = y[b0 + tid];

    float acc[8][4];
    #pragma unroll
    for (int j = 0; j < 8; j++)
        #pragma unroll
        for (int q = 0; q < 4; q++) acc[j][q] = 0.f;

    uint32_t aBase, aX;
    const int aRowL = lane & 15, aHalf = (lane >> 4) * 16;
    {
        int r = warp_m * 16 + aRowL;
        aBase = r * 128; aX = (r & 7) << 4;
    }
    uint32_t bBase[4], bX[4];
    const int bRowL = ((lane >> 4) << 3) | (lane & 7);
    const int bHalf = ((lane >> 3) & 1) * 16;
    #pragma unroll
    for (int np = 0; np < 4; np++) {
        int r = warp_n * 64 + np * 16 + bRowL;
        bBase[np] = 4096 + r * 128; bX[np] = (r & 7) << 4;
    }

    // stage = 36KB: A 32x64 bf16 (4KB) + B 256x64 bf16 (32KB)
    auto load_stage = [&](int buf, int k0) {
        uint32_t aB = smB + buf * 36864;
        uint32_t bB = aB + 4096;
        {
            int m = tid >> 3, kq = tid & 7;
            uint32_t byteo = m * 128 + kq * 16;
            CP_ASYNC16(aB + SW(byteo), Asrc + (size_t)m * D_ + k0 + kq * 8);
        }
        #pragma unroll
        for (int l = 0; l < 8; l++) {
            int idx = tid + l * 256;
            int n = idx >> 3, kq = idx & 7;
            uint32_t byteo = n * 128 + kq * 16;
            CP_ASYNC16(bB + SW(byteo), g_ub + (size_t)n * D_ + k0 + kq * 8);
        }
        CP_COMMIT();
    };

    load_stage(0, 0);
    load_stage(1, 64);
    for (int it = 0; it < 8; it++) {
        if (it == 7) CP_WAIT(0); else CP_WAIT(1);
        __syncthreads();
        if (it + 2 < 8) load_stage((it + 2) % 3, (it + 2) * 64);
        uint32_t stage = smB + (uint32_t)(it % 3) * 36864;
        #pragma unroll
        for (int ks = 0; ks < 4; ks++) {
            uint32_t kb = ks * 32;
            uint32_t a[4], b[4][4];
            LDSM_X4(a, stage + aBase + ((kb + aHalf) ^ aX));
            #pragma unroll
            for (int np = 0; np < 4; np++)
                LDSM_X4(b[np], stage + bBase[np] + ((kb + bHalf) ^ bX[np]));
            #pragma unroll
            for (int nt = 0; nt < 8; nt++)
                MMA_BF16(acc[nt], a, (&b[nt >> 1][(nt & 1) * 2]));
        }
    }

    // ---- fused epilogue ----
    {
        int rl = warp_m * 16 + r4;
        int y0 = ys_s[rl], y8 = ys_s[rl + 8];
        float p0 = INFINITY, n0v = INFINITY, p8 = INFINITY, n8v = INFINITY;
        #pragma unroll
        for (int nt = 0; nt < 8; nt++) {
            #pragma unroll
            for (int q = 0; q < 2; q++) {
                int p = warp_n * 64 + nt * 8 + kq4 * 2 + q;
                int lb = lab_s[p];
                float pp = p2_s[p];
                float d0 = x2s[lb][rl]     + pp - 2.0f * acc[nt][q];
                float d8 = x2s[lb][rl + 8] + pp - 2.0f * acc[nt][2 + q];
                if (lb == y0) p0 = fminf(p0, d0); else n0v = fminf(n0v, d0);
                if (lb == y8) p8 = fminf(p8, d8); else n8v = fminf(n8v, d8);
            }
        }
        #pragma unroll
        for (int off = 1; off < 4; off <<= 1) {
            p0  = fminf(p0,  __shfl_xor_sync(0xffffffffu, p0,  off));
            n0v = fminf(n0v, __shfl_xor_sync(0xffffffffu, n0v, off));
            p8  = fminf(p8,  __shfl_xor_sync(0xffffffffu, p8,  off));
            n8v = fminf(n8v, __shfl_xor_sync(0xffffffffu, n8v, off));
        }
        if (kq4 == 0) {
            pos_s[warp_n][rl]     = p0;  neg_s[warp_n][rl]     = n0v;
            pos_s[warp_n][rl + 8] = p8;  neg_s[warp_n][rl + 8] = n8v;
        }
    }
    __syncthreads();
    if (tid < 32) {
        float pos = fminf(fminf(pos_s[0][tid], pos_s[1][tid]),
                          fminf(pos_s[2][tid], pos_s[3][tid]));
        float neg = fminf(fminf(neg_s[0][tid], neg_s[1][tid]),
                          fminf(neg_s[2][tid], neg_s[3][tid]));
        float mu = (pos - neg) / (pos + neg);
        float sg = 1.0f / (1.0f + expf(-mu));
        #pragma unroll
        for (int off = 16; off; off >>= 1) sg += __shfl_xor_sync(0xffffffffu, sg, off);
        if (tid == 0) g_sg[blockIdx.x] = sg;
    }
}

__global__ void norm_kernel(const float* __restrict__ omega) {
    float s = 0.f;
    int n = C_ * D_ * D_;
    for (int i = blockIdx.x * blockDim.x + threadIdx.x; i < n; i += gridDim.x * blockDim.x) {
        float v = omega[i];
        s += v * v;
    }
    #pragma unroll
    for (int off = 16; off; off >>= 1) s += __shfl_xor_sync(0xffffffffu, s, off);
    __shared__ float ws[8];
    int lane = threadIdx.x & 31, w = threadIdx.x >> 5;
    if (lane == 0) ws[w] = s;
    __syncthreads();
    if (threadIdx.x == 0) {
        float t = 0.f;
        #pragma unroll
        for (int i = 0; i < 8; i++) t += ws[i];
        g_norm[blockIdx.x] = t;
    }
}

// single block: sum sigmoid partials (128) + norm partials (512), emit loss
__global__ __launch_bounds__(256) void final_kernel(float* out) {
    int tid = threadIdx.x;
    float sg = 0.f, nm = 0.f;
    if (tid < B_ / 32) sg = g_sg[tid];
    nm = g_norm[tid] + g_norm[tid + 256];
    #pragma unroll
    for (int off = 16; off; off >>= 1) {
        sg += __shfl_xor_sync(0xffffffffu, sg, off);
        nm += __shfl_xor_sync(0xffffffffu, nm, off);
    }
    __shared__ float ss[8], sn[8];
    int lane = tid & 31, w = tid >> 5;
    if (lane == 0) { ss[w] = sg; sn[w] = nm; }
    __syncthreads();
    if (tid == 0) {
        float a = 0.f, b = 0.f;
        #pragma unroll
        for (int i = 0; i < 8; i++) { a += ss[i]; b += sn[i]; }
        out[0] = a * (1.0f / (float)B_) + 0.01f * sqrtf(b);
    }
}

// ===========================================================================
extern "C" void kernel_launch(void* const* d_in, const int* in_sizes, int n_in,
                              void* d_out, int out_size) {
    const float* x      = (const float*)d_in[0];
    const int*   y      = (const int*)d_in[1];
    const float* protos = (const float*)d_in[2];
    const float* omega  = (const float*)d_in[3];
    const int*   labels = (const int*)d_in[4];
    float* out = (float*)d_out;

    static cudaStream_t s2 = nullptr;
    static cudaEvent_t evA = nullptr, evB = nullptr, evE = nullptr, evN = nullptr;
    static __nv_bfloat16* p_ub = nullptr;
    static float* p_u = nullptr;
    if (s2 == nullptr) {                 // first (uncaptured) call only
        cudaStreamCreateWithFlags(&s2, cudaStreamNonBlocking);
        cudaEventCreateWithFlags(&evA, cudaEventDisableTiming);
        cudaEventCreateWithFlags(&evB, cudaEventDisableTiming);
        cudaEventCreateWithFlags(&evE, cudaEventDisableTiming);
        cudaEventCreateWithFlags(&evN, cudaEventDisableTiming);
        cudaFuncSetAttribute(x2_mma_kernel,
                             cudaFuncAttributeMaxDynamicSharedMemorySize, 98304);
        cudaFuncSetAttribute(dist_mma_kernel,
                             cudaFuncAttributeMaxDynamicSharedMemorySize, 110592);
        cudaGetSymbolAddress((void**)&p_ub,  g_ub);
        cudaGetSymbolAddress((void**)&p_u,   g_u);
    }

    cudaEventRecord(evA, 0);
    cudaStreamWaitEvent(s2, evA, 0);

    // main stream: convert X (bf16 + fp8 + rowsq), wait E, x2, dist, final
    convx_kernel<<<B_ / 8, 256>>>(x);

    // side stream: convert E first (gates x2), then prototype chain
    conve_kernel<<<C_ * D_ * D_ / 4 / 256, 256, 0, s2>>>(omega);
    cudaEventRecord(evE, s2);

    cudaStreamWaitEvent(0, evE, 0);
    x2_mma_kernel<<<dim3(B_ / 128, 4, C_), 256, 98304>>>(x);

    zero_side_kernel<<<(P_ * D_ + 255) / 256, 256, 0, s2>>>();
    tp_kernel<<<dim3(D_ / 32, C_, 4), 256, 0, s2>>>(omega, protos);
    p2_kernel<<<P_, 128, 0, s2>>>();
    u_kernel<<<dim3(D_ / 32, C_, 4), 256, 0, s2>>>(omega);
    f2bf_kernel<<<(P_ * D_ / 4 + 255) / 256, 256, 0, s2>>>(p_u, p_ub, P_ * D_ / 4);
    cudaEventRecord(evB, s2);          // everything dist needs is ready
    norm_kernel<<<512, 256, 0, s2>>>(omega);
    cudaEventRecord(evN, s2);          // norm only gates final

    cudaStreamWaitEvent(0, evB, 0);
    dist_mma_kernel<<<B_ / 32, 256, 110592>>>(y, labels);
    cudaStreamWaitEvent(0, evN, 0);
    final_kernel<<<1, 256>>>(out);
}

// round 13
// speedup vs baseline: 1.7548x; 1.7548x over previous
#include <cuda_runtime.h>
#include <cuda_bf16.h>
#include <math.h>
#include <stdint.h>

#define B_ 4096
#define D_ 512
#define P_ 256
#define C_ 8

// ---------------- scratch (device globals; no allocation allowed) ----------
__device__ __align__(128) float g_tp[P_ * D_];   // tp[p,i] = omega[c_p] @ w[p]
__device__ __align__(128) float g_u[P_ * D_];    // u[p,j]  = omega[c_p]^T @ tp[p]
__device__ float g_p2[P_];                       // ||tp_p||^2
__device__ __align__(128) float g_x2p[4][C_][B_]; // x2 partials per n-block
__device__ float g_sg[B_ / 32];                  // per-dist-CTA sigmoid sums
__device__ float g_norm[2048];                   // norm partials (from convom)
__device__ unsigned int g_ctr;                   // dist completion counter
__device__ __align__(128) __nv_bfloat16 g_xb[B_ * D_];        // X bf16
__device__ __align__(128) __nv_bfloat16 g_omb[C_ * D_ * D_];  // omega bf16
__device__ __align__(128) __nv_bfloat16 g_ub[P_ * D_];        // u bf16

// ======================= helpers ===========================================
__device__ __forceinline__ uint32_t smem_u32(const void* p) {
    uint32_t a;
    asm("{ .reg .u64 t; cvta.to.shared.u64 t, %1; cvt.u32.u64 %0, t; }"
        : "=r"(a) : "l"(p));
    return a;
}

#define CP_ASYNC16(dst, src) \
    asm volatile("cp.async.cg.shared.global [%0], [%1], 16;" \
                 :: "r"(dst), "l"(src) : "memory")
#define CP_COMMIT() asm volatile("cp.async.commit_group;" ::: "memory")
#define CP_WAIT(n)  asm volatile("cp.async.wait_group %0;" :: "n"(n) : "memory")

// SW128-style swizzle (rows are 128 bytes)
#define SW(b) ((b) ^ (((b) >> 3) & 0x70))

#define MMA_BF16(d, a, b) \
    asm volatile("mma.sync.aligned.m16n8k16.row.col.f32.bf16.bf16.f32 " \
        "{%0,%1,%2,%3}, {%4,%5,%6,%7}, {%8,%9}, {%0,%1,%2,%3};" \
        : "+f"((d)[0]), "+f"((d)[1]), "+f"((d)[2]), "+f"((d)[3]) \
        : "r"((a)[0]), "r"((a)[1]), "r"((a)[2]), "r"((a)[3]), \
          "r"((b)[0]), "r"((b)[1]))

#define LDSM_X4(r, addr) \
    asm volatile("ldmatrix.sync.aligned.m8n8.x4.shared.b16 {%0,%1,%2,%3}, [%4];" \
        : "=r"((r)[0]), "=r"((r)[1]), "=r"((r)[2]), "=r"((r)[3]) : "r"(addr))

// ===========================================================================
// side-stream zero of tp/u accumulators + dist completion counter
__global__ void zero_side_kernel() {
    int i = blockIdx.x * blockDim.x + threadIdx.x;
    if (i < P_ * D_) { g_tp[i] = 0.0f; g_u[i] = 0.0f; }
    if (i == 0) g_ctr = 0u;
}

__global__ __launch_bounds__(256) void f2bf_kernel(const float* __restrict__ s,
                                                   __nv_bfloat16* __restrict__ d,
                                                   int n4) {
    int i = blockIdx.x * blockDim.x + threadIdx.x;
    if (i < n4) {
        float4 v = ((const float4*)s)[i];
        __nv_bfloat162 lo = __floats2bfloat162_rn(v.x, v.y);
        __nv_bfloat162 hi = __floats2bfloat162_rn(v.z, v.w);
        uint2 o = {*(uint32_t*)&lo, *(uint32_t*)&hi};
        ((uint2*)d)[i] = o;
    }
}

// omega convert: fp32 -> bf16, fused Frobenius-norm partials (one read pass)
__global__ __launch_bounds__(256) void convom_kernel(const float* __restrict__ om) {
    int i = blockIdx.x * blockDim.x + threadIdx.x;   // float4 index, exact grid
    float4 v = ((const float4*)om)[i];
    __nv_bfloat162 lo = __floats2bfloat162_rn(v.x, v.y);
    __nv_bfloat162 hi = __floats2bfloat162_rn(v.z, v.w);
    uint2 o = {*(uint32_t*)&lo, *(uint32_t*)&hi};
    ((uint2*)g_omb)[i] = o;
    float s = v.x * v.x + v.y * v.y + v.z * v.z + v.w * v.w;
    #pragma unroll
    for (int off = 16; off; off >>= 1) s += __shfl_xor_sync(0xffffffffu, s, off);
    __shared__ float ws[8];
    int lane = threadIdx.x & 31, w = threadIdx.x >> 5;
    if (lane == 0) ws[w] = s;
    __syncthreads();
    if (threadIdx.x == 0) {
        float t = 0.f;
        #pragma unroll
        for (int k = 0; k < 8; k++) t += ws[k];
        g_norm[blockIdx.x] = t;
    }
}

// tp[p,i] = sum_j omega[c,i,j] * w[p,j]; split-K x4 via atomicAdd
__global__ __launch_bounds__(256) void tp_kernel(const float* __restrict__ omega,
                                                 const float* __restrict__ protos) {
    int c = blockIdx.y;
    int i0 = blockIdx.x * 32;
    int ks = blockIdx.z;
    int tid = threadIdx.x;
    int tx = tid & 31;
    int ty = tid >> 5;
    __shared__ float w_s[32][33];
    __shared__ float om_s[32][33];
    float acc[4] = {0.f, 0.f, 0.f, 0.f};
    for (int t = 0; t < 4; t++) {
        int j0 = ks * 128 + t * 32;
        #pragma unroll
        for (int l = 0; l < 4; l++) {
            int s = tid + l * 256;
            int r = s >> 5, jj = s & 31;
            w_s[r][jj]  = protos[(r * 8 + c) * D_ + j0 + jj];
            om_s[r][jj] = omega[((size_t)c * D_ + i0 + r) * D_ + j0 + jj];
        }
        __syncthreads();
        #pragma unroll
        for (int jj = 0; jj < 32; jj++) {
            float wv = w_s[tx][jj];
            #pragma unroll
            for (int r = 0; r < 4; r++)
                acc[r] += om_s[ty * 4 + r][jj] * wv;
        }
        __syncthreads();
    }
    #pragma unroll
    for (int r = 0; r < 4; r++)
        atomicAdd(&g_tp[(tx * 8 + c) * D_ + i0 + ty * 4 + r], acc[r]);
}

// u[p,j] = sum_i tp[p,i] * omega[c,i,j]; split-K x4 via atomicAdd
__global__ __launch_bounds__(256) void u_kernel(const float* __restrict__ omega) {
    int c = blockIdx.y, j0 = blockIdx.x * 32;
    int ks = blockIdx.z;
    int tid = threadIdx.x;
    int jx = tid & 7;
    int py = tid >> 3;
    __shared__ float tp_s[32][33];
    __shared__ float om_s[32][32];
    float ax = 0.f, ay = 0.f, az = 0.f, aw = 0.f;
    for (int t = 0; t < 4; t++) {
        int i0 = ks * 128 + t * 32;
        #pragma unroll
        for (int l = 0; l < 4; l++) {
            int s = tid + l * 256;
            int p = s >> 5, ii = s & 31;
            tp_s[p][ii] = g_tp[(p * 8 + c) * D_ + i0 + ii];
        }
        #pragma unroll
        for (int l = 0; l < 4; l++) {
            int s = tid + l * 256;
            int ii = s >> 5, jj = s & 31;
            om_s[ii][jj] = omega[((size_t)c * D_ + i0 + ii) * D_ + j0 + jj];
        }
        __syncthreads();
        #pragma unroll
        for (int ii = 0; ii < 32; ii++) {
            float tv = tp_s[py][ii];
            float4 ov = *(const float4*)&om_s[ii][jx * 4];
            ax += tv * ov.x; ay += tv * ov.y; az += tv * ov.z; aw += tv * ov.w;
        }
        __syncthreads();
    }
    float* dst = &g_u[(size_t)(py * 8 + c) * D_ + j0 + jx * 4];
    atomicAdd(dst + 0, ax);
    atomicAdd(dst + 1, ay);
    atomicAdd(dst + 2, az);
    atomicAdd(dst + 3, aw);
}

__global__ void p2_kernel() {
    int p = blockIdx.x;
    int tid = threadIdx.x;
    float s = 0.f;
    for (int i = tid; i < D_; i += 128) {
        float v = g_tp[p * D_ + i];
        s += v * v;
    }
    #pragma unroll
    for (int off = 16; off; off >>= 1) s += __shfl_xor_sync(0xffffffffu, s, off);
    __shared__ float ws[4];
    if ((tid & 31) == 0) ws[tid >> 5] = s;
    __syncthreads();
    if (tid == 0) g_p2[p] = ws[0] + ws[1] + ws[2] + ws[3];
}

// ================= x2 via mma.sync bf16 + ldmatrix =========================
// CTA 128m x 128n x K=512 (BK=64), 8 warps (2m x 4n), warp tile 64x32,
// 3-stage cp.async pipeline. Epilogue: rowwise sumsq, cross-warp_n smem
// reduction, one coalesced store per row into g_x2p[ny] (no atomics).
__global__ __launch_bounds__(256) void x2_mma_kernel() {
    extern __shared__ char sm[];
    __shared__ float red[4][128];   // [warp_n][local row]
    const int tid = threadIdx.x, lane = tid & 31, wid = tid >> 5;
    const int warp_m = wid & 1, warp_n = wid >> 1;
    const int b0 = blockIdx.x * 128, ny = blockIdx.y, c = blockIdx.z;
    const int n0 = ny * 128;
    const int r4 = lane >> 2, kq4 = lane & 3;

    const __nv_bfloat16* Asrc = g_xb + (size_t)b0 * D_;
    const __nv_bfloat16* Bsrc = g_omb + (size_t)c * D_ * D_ + (size_t)n0 * D_;
    uint32_t smB = smem_u32(sm);

    float acc[4][4][4];
    #pragma unroll
    for (int i = 0; i < 4; i++)
        #pragma unroll
        for (int j = 0; j < 4; j++)
            #pragma unroll
            for (int q = 0; q < 4; q++) acc[i][j][q] = 0.f;

    uint32_t aBase[4], aX[4];
    const int aRowL = lane & 15, aHalf = (lane >> 4) * 16;
    #pragma unroll
    for (int mt = 0; mt < 4; mt++) {
        int r = warp_m * 64 + mt * 16 + aRowL;
        aBase[mt] = r * 128; aX[mt] = (r & 7) << 4;
    }
    uint32_t bBase[2], bX[2];
    const int bRowL = ((lane >> 4) << 3) | (lane & 7);
    const int bHalf = ((lane >> 3) & 1) * 16;
    #pragma unroll
    for (int np = 0; np < 2; np++) {
        int r = warp_n * 32 + np * 16 + bRowL;
        bBase[np] = 16384 + r * 128; bX[np] = (r & 7) << 4;
    }

    // stage = 32KB: A 128x64 bf16 (16KB) + B 128x64 bf16 (16KB)
    auto load_stage = [&](int buf, int k0) {
        uint32_t aB = smB + buf * 32768;
        uint32_t bB = aB + 16384;
        #pragma unroll
        for (int l = 0; l < 4; l++) {
            int idx = tid + l * 256;
            int m = idx >> 3, kq = idx & 7;
            uint32_t byteo = m * 128 + kq * 16;
            CP_ASYNC16(aB + SW(byteo), Asrc + (size_t)m * D_ + k0 + kq * 8);
        }
        #pragma unroll
        for (int l = 0; l < 4; l++) {
            int idx = tid + l * 256;
            int n = idx >> 3, kq = idx & 7;
            uint32_t byteo = n * 128 + kq * 16;
            CP_ASYNC16(bB + SW(byteo), Bsrc + (size_t)n * D_ + k0 + kq * 8);
        }
        CP_COMMIT();
    };

    load_stage(0, 0);
    load_stage(1, 64);
    for (int it = 0; it < 8; it++) {
        if (it == 7) CP_WAIT(0); else CP_WAIT(1);
        __syncthreads();
        if (it + 2 < 8) load_stage((it + 2) % 3, (it + 2) * 64);
        uint32_t stage = smB + (uint32_t)(it % 3) * 32768;
        #pragma unroll
        for (int ks = 0; ks < 4; ks++) {
            uint32_t kb = ks * 32;
            uint32_t a[4][4], b[2][4];
            #pragma unroll
            for (int mt = 0; mt < 4; mt++)
                LDSM_X4(a[mt], stage + aBase[mt] + ((kb + aHalf) ^ aX[mt]));
            #pragma unroll
            for (int np = 0; np < 2; np++)
                LDSM_X4(b[np], stage + bBase[np] + ((kb + bHalf) ^ bX[np]));
            #pragma unroll
            for (int mt = 0; mt < 4; mt++)
                #pragma unroll
                for (int nt = 0; nt < 4; nt++)
                    MMA_BF16(acc[mt][nt], a[mt], (&b[nt >> 1][(nt & 1) * 2]));
        }
    }

    // epilogue: per-warp rowwise sumsq partials (32 n-cols each) ->
    // smem reduce across the 4 warp_n groups -> one store per row.
    #pragma unroll
    for (int mt = 0; mt < 4; mt++) {
        float s0 = 0.f, s8 = 0.f;
        #pragma unroll
        for (int nt = 0; nt < 4; nt++) {
            s0 += acc[mt][nt][0] * acc[mt][nt][0] + acc[mt][nt][1] * acc[mt][nt][1];
            s8 += acc[mt][nt][2] * acc[mt][nt][2] + acc[mt][nt][3] * acc[mt][nt][3];
        }
        s0 += __shfl_xor_sync(0xffffffffu, s0, 1);
        s0 += __shfl_xor_sync(0xffffffffu, s0, 2);
        s8 += __shfl_xor_sync(0xffffffffu, s8, 1);
        s8 += __shfl_xor_sync(0xffffffffu, s8, 2);
        if (kq4 == 0) {
            int rl = warp_m * 64 + mt * 16 + r4;
            red[warp_n][rl]     = s0;
            red[warp_n][rl + 8] = s8;
        }
    }
    __syncthreads();
    if (tid < 128)
        g_x2p[ny][c][b0 + tid] = red[0][tid] + red[1][tid]
                               + red[2][tid] + red[3][tid];
}

// ============== dist via mma.sync bf16 + ldmatrix, fused epilogue ==========
// CTA 32m x 256n x 512 (BK=64), 8 warps (2m x 4n), warp tile 16x64.
// Last CTA (atomic counter) also performs the final loss reduction.
__global__ __launch_bounds__(256) void dist_mma_kernel(const int* __restrict__ y,
                                                       const int* __restrict__ labels,
                                                       float* __restrict__ out) {
    extern __shared__ char sm[];
    __shared__ float x2s[C_][32];
    __shared__ float p2_s[P_];
    __shared__ int   lab_s[P_];
    __shared__ int   ys_s[32];
    __shared__ float pos_s[4][32];
    __shared__ float neg_s[4][32];
    __shared__ bool  isLast;

    const int tid = threadIdx.x, lane = tid & 31, wid = tid >> 5;
    const int warp_m = wid & 1, warp_n = wid >> 1;
    const int b0 = blockIdx.x * 32;
    const int r4 = lane >> 2, kq4 = lane & 3;

    const __nv_bfloat16* Asrc = g_xb + (size_t)b0 * D_;
    uint32_t smB = smem_u32(sm);

    for (int i = tid; i < P_; i += 256) {
        p2_s[i]  = g_p2[i];
        lab_s[i] = labels[i];
    }
    if (tid < C_ * 32) {
        int c = tid >> 5, r = tid & 31;
        x2s[c][r] = g_x2p[0][c][b0 + r] + g_x2p[1][c][b0 + r]
                  + g_x2p[2][c][b0 + r] + g_x2p[3][c][b0 + r];
    }
    if (tid < 32) ys_s[tid] = y[b0 + tid];

    float acc[8][4];
    #pragma unroll
    for (int j = 0; j < 8; j++)
        #pragma unroll
        for (int q = 0; q < 4; q++) acc[j][q] = 0.f;

    uint32_t aBase, aX;
    const int aRowL = lane & 15, aHalf = (lane >> 4) * 16;
    {
        int r = warp_m * 16 + aRowL;
        aBase = r * 128; aX = (r & 7) << 4;
    }
    uint32_t bBase[4], bX[4];
    const int bRowL = ((lane >> 4) << 3) | (lane & 7);
    const int bHalf = ((lane >> 3) & 1) * 16;
    #pragma unroll
    for (int np = 0; np < 4; np++) {
        int r = warp_n * 64 + np * 16 + bRowL;
        bBase[np] = 4096 + r * 128; bX[np] = (r & 7) << 4;
    }

    // stage = 36KB: A 32x64 bf16 (4KB) + B 256x64 bf16 (32KB)
    auto load_stage = [&](int buf, int k0) {
        uint32_t aB = smB + buf * 36864;
        uint32_t bB = aB + 4096;
        {
            int m = tid >> 3, kq = tid & 7;
            uint32_t byteo = m * 128 + kq * 16;
            CP_ASYNC16(aB + SW(byteo), Asrc + (size_t)m * D_ + k0 + kq * 8);
        }
        #pragma unroll
        for (int l = 0; l < 8; l++) {
            int idx = tid + l * 256;
            int n = idx >> 3, kq = idx & 7;
            uint32_t byteo = n * 128 + kq * 16;
            CP_ASYNC16(bB + SW(byteo), g_ub + (size_t)n * D_ + k0 + kq * 8);
        }
        CP_COMMIT();
    };

    load_stage(0, 0);
    load_stage(1, 64);
    for (int it = 0; it < 8; it++) {
        if (it == 7) CP_WAIT(0); else CP_WAIT(1);
        __syncthreads();
        if (it + 2 < 8) load_stage((it + 2) % 3, (it + 2) * 64);
        uint32_t stage = smB + (uint32_t)(it % 3) * 36864;
        #pragma unroll
        for (int ks = 0; ks < 4; ks++) {
            uint32_t kb = ks * 32;
            uint32_t a[4], b[4][4];
            LDSM_X4(a, stage + aBase + ((kb + aHalf) ^ aX));
            #pragma unroll
            for (int np = 0; np < 4; np++)
                LDSM_X4(b[np], stage + bBase[np] + ((kb + bHalf) ^ bX[np]));
            #pragma unroll
            for (int nt = 0; nt < 8; nt++)
                MMA_BF16(acc[nt], a, (&b[nt >> 1][(nt & 1) * 2]));
        }
    }

    // ---- fused epilogue ----
    {
        int rl = warp_m * 16 + r4;
        int y0 = ys_s[rl], y8 = ys_s[rl + 8];
        float p0 = INFINITY, n0v = INFINITY, p8 = INFINITY, n8v = INFINITY;
        #pragma unroll
        for (int nt = 0; nt < 8; nt++) {
            #pragma unroll
            for (int q = 0; q < 2; q++) {
                int p = warp_n * 64 + nt * 8 + kq4 * 2 + q;
                int lb = lab_s[p];
                float pp = p2_s[p];
                float d0 = x2s[lb][rl]     + pp - 2.0f * acc[nt][q];
                float d8 = x2s[lb][rl + 8] + pp - 2.0f * acc[nt][2 + q];
                if (lb == y0) p0 = fminf(p0, d0); else n0v = fminf(n0v, d0);
                if (lb == y8) p8 = fminf(p8, d8); else n8v = fminf(n8v, d8);
            }
        }
        #pragma unroll
        for (int off = 1; off < 4; off <<= 1) {
            p0  = fminf(p0,  __shfl_xor_sync(0xffffffffu, p0,  off));
            n0v = fminf(n0v, __shfl_xor_sync(0xffffffffu, n0v, off));
            p8  = fminf(p8,  __shfl_xor_sync(0xffffffffu, p8,  off));
            n8v = fminf(n8v, __shfl_xor_sync(0xffffffffu, n8v, off));
        }
        if (kq4 == 0) {
            pos_s[warp_n][rl]     = p0;  neg_s[warp_n][rl]     = n0v;
            pos_s[warp_n][rl + 8] = p8;  neg_s[warp_n][rl + 8] = n8v;
        }
    }
    __syncthreads();
    if (tid < 32) {
        float pos = fminf(fminf(pos_s[0][tid], pos_s[1][tid]),
                          fminf(pos_s[2][tid], pos_s[3][tid]));
        float neg = fminf(fminf(neg_s[0][tid], neg_s[1][tid]),
                          fminf(neg_s[2][tid], neg_s[3][tid]));
        float mu = (pos - neg) / (pos + neg);
        float sg = 1.0f / (1.0f + expf(-mu));
        #pragma unroll
        for (int off = 16; off; off >>= 1) sg += __shfl_xor_sync(0xffffffffu, sg, off);
        if (tid == 0) g_sg[blockIdx.x] = sg;
    }

    // ---- last-CTA final reduction (replaces final_kernel) ----
    __threadfence();
    if (tid == 0) isLast = (atomicAdd(&g_ctr, 1u) == (unsigned)(B_ / 32 - 1));
    __syncthreads();
    if (isLast) {
        float sg = 0.f, nm = 0.f;
        if (tid < B_ / 32) sg = g_sg[tid];
        #pragma unroll
        for (int k = 0; k < 8; k++) nm += g_norm[tid + k * 256];
        #pragma unroll
        for (int off = 16; off; off >>= 1) {
            sg += __shfl_xor_sync(0xffffffffu, sg, off);
            nm += __shfl_xor_sync(0xffffffffu, nm, off);
        }
        __shared__ float ss[8], sn[8];
        if (lane == 0) { ss[wid] = sg; sn[wid] = nm; }
        __syncthreads();
        if (tid == 0) {
            float a = 0.f, b = 0.f;
            #pragma unroll
            for (int k = 0; k < 8; k++) { a += ss[k]; b += sn[k]; }
            out[0] = a * (1.0f / (float)B_) + 0.01f * sqrtf(b);
        }
    }
}

// ===========================================================================
extern "C" void kernel_launch(void* const* d_in, const int* in_sizes, int n_in,
                              void* d_out, int out_size) {
    const float* x      = (const float*)d_in[0];
    const int*   y      = (const int*)d_in[1];
    const float* protos = (const float*)d_in[2];
    const float* omega  = (const float*)d_in[3];
    const int*   labels = (const int*)d_in[4];
    float* out = (float*)d_out;

    static cudaStream_t s2 = nullptr;
    static cudaEvent_t evA = nullptr, evB = nullptr, evC = nullptr;
    static __nv_bfloat16* p_xb = nullptr;
    static __nv_bfloat16* p_ub = nullptr;
    static float* p_u = nullptr;
    if (s2 == nullptr) {                 // first (uncaptured) call only
        cudaStreamCreateWithFlags(&s2, cudaStreamNonBlocking);
        cudaEventCreateWithFlags(&evA, cudaEventDisableTiming);
        cudaEventCreateWithFlags(&evB, cudaEventDisableTiming);
        cudaEventCreateWithFlags(&evC, cudaEventDisableTiming);
        cudaFuncSetAttribute(x2_mma_kernel,
                             cudaFuncAttributeMaxDynamicSharedMemorySize, 98304);
        cudaFuncSetAttribute(dist_mma_kernel,
                             cudaFuncAttributeMaxDynamicSharedMemorySize, 110592);
        cudaGetSymbolAddress((void**)&p_xb,  g_xb);
        cudaGetSymbolAddress((void**)&p_ub,  g_ub);
        cudaGetSymbolAddress((void**)&p_u,   g_u);
    }

    cudaEventRecord(evA, 0);
    cudaStreamWaitEvent(s2, evA, 0);

    // main stream: convert X, wait for omega (side), x2, dist(writes out)
    f2bf_kernel<<<(B_ * D_ / 4 + 255) / 256, 256>>>(x, p_xb, B_ * D_ / 4);

    // side stream: omega convert + fused norm partials (gates x2), then
    // prototype chain
    convom_kernel<<<C_ * D_ * D_ / 4 / 256, 256, 0, s2>>>(omega);
    cudaEventRecord(evC, s2);

    cudaStreamWaitEvent(0, evC, 0);
    x2_mma_kernel<<<dim3(B_ / 128, 4, C_), 256, 98304>>>();

    zero_side_kernel<<<(P_ * D_ + 255) / 256, 256, 0, s2>>>();
    tp_kernel<<<dim3(D_ / 32, C_, 4), 256, 0, s2>>>(omega, protos);
    p2_kernel<<<P_, 128, 0, s2>>>();
    u_kernel<<<dim3(D_ / 32, C_, 4), 256, 0, s2>>>(omega);
    f2bf_kernel<<<(P_ * D_ / 4 + 255) / 256, 256, 0, s2>>>(p_u, p_ub, P_ * D_ / 4);
    cudaEventRecord(evB, s2);          // everything dist needs is ready

    cudaStreamWaitEvent(0, evB, 0);
    dist_mma_kernel<<<B_ / 32, 256, 110592>>>(y, labels, out);
}

// round 14
// speedup vs baseline: 1.8534x; 1.0562x over previous
#include <cuda_runtime.h>
#include <cuda_bf16.h>
#include <math.h>
#include <stdint.h>

#define B_ 4096
#define D_ 512
#define P_ 256
#define C_ 8

// ---------------- scratch (device globals; no allocation allowed) ----------
__device__ __align__(128) float g_tp[P_ * D_];   // tp[p,i] = omega[c_p] @ w[p]
__device__ __align__(128) float g_u[P_ * D_];    // u[p,j]  = omega[c_p]^T @ tp[p]
__device__ float g_p2[P_];                       // ||tp_p||^2
__device__ __align__(128) float g_x2p[4][C_][B_]; // x2 partials per n-block
__device__ float g_sg[B_ / 32];                  // per-dist-CTA sigmoid sums
__device__ float g_norm[2048];                   // norm partials (from convom)
__device__ unsigned int g_ctr;                   // dist completion counter
__device__ __align__(128) __nv_bfloat16 g_xb[B_ * D_];        // X bf16
__device__ __align__(128) __nv_bfloat16 g_omb[C_ * D_ * D_];  // omega bf16
__device__ __align__(128) __nv_bfloat16 g_ub[P_ * D_];        // u bf16

// ======================= helpers ===========================================
__device__ __forceinline__ uint32_t smem_u32(const void* p) {
    uint32_t a;
    asm("{ .reg .u64 t; cvta.to.shared.u64 t, %1; cvt.u32.u64 %0, t; }"
        : "=r"(a) : "l"(p));
    return a;
}

#define CP_ASYNC16(dst, src) \
    asm volatile("cp.async.cg.shared.global [%0], [%1], 16;" \
                 :: "r"(dst), "l"(src) : "memory")
#define CP_COMMIT() asm volatile("cp.async.commit_group;" ::: "memory")
#define CP_WAIT(n)  asm volatile("cp.async.wait_group %0;" :: "n"(n) : "memory")

// SW128-style swizzle (rows are 128 bytes)
#define SW(b) ((b) ^ (((b) >> 3) & 0x70))

#define MMA_BF16(d, a, b) \
    asm volatile("mma.sync.aligned.m16n8k16.row.col.f32.bf16.bf16.f32 " \
        "{%0,%1,%2,%3}, {%4,%5,%6,%7}, {%8,%9}, {%0,%1,%2,%3};" \
        : "+f"((d)[0]), "+f"((d)[1]), "+f"((d)[2]), "+f"((d)[3]) \
        : "r"((a)[0]), "r"((a)[1]), "r"((a)[2]), "r"((a)[3]), \
          "r"((b)[0]), "r"((b)[1]))

#define LDSM_X4(r, addr) \
    asm volatile("ldmatrix.sync.aligned.m8n8.x4.shared.b16 {%0,%1,%2,%3}, [%4];" \
        : "=r"((r)[0]), "=r"((r)[1]), "=r"((r)[2]), "=r"((r)[3]) : "r"(addr))

// ===========================================================================
// side-stream zero of tp/u accumulators + dist completion counter
__global__ void zero_side_kernel() {
    int i = blockIdx.x * blockDim.x + threadIdx.x;
    if (i < P_ * D_) { g_tp[i] = 0.0f; g_u[i] = 0.0f; }
    if (i == 0) g_ctr = 0u;
}

__global__ __launch_bounds__(256) void f2bf_kernel(const float* __restrict__ s,
                                                   __nv_bfloat16* __restrict__ d,
                                                   int n4) {
    int i = blockIdx.x * blockDim.x + threadIdx.x;
    if (i < n4) {
        float4 v = ((const float4*)s)[i];
        __nv_bfloat162 lo = __floats2bfloat162_rn(v.x, v.y);
        __nv_bfloat162 hi = __floats2bfloat162_rn(v.z, v.w);
        uint2 o = {*(uint32_t*)&lo, *(uint32_t*)&hi};
        ((uint2*)d)[i] = o;
    }
}

// omega convert: fp32 -> bf16, fused Frobenius-norm partials (one read pass)
__global__ __launch_bounds__(256) void convom_kernel(const float* __restrict__ om) {
    int i = blockIdx.x * blockDim.x + threadIdx.x;   // float4 index, exact grid
    float4 v = ((const float4*)om)[i];
    __nv_bfloat162 lo = __floats2bfloat162_rn(v.x, v.y);
    __nv_bfloat162 hi = __floats2bfloat162_rn(v.z, v.w);
    uint2 o = {*(uint32_t*)&lo, *(uint32_t*)&hi};
    ((uint2*)g_omb)[i] = o;
    float s = v.x * v.x + v.y * v.y + v.z * v.z + v.w * v.w;
    #pragma unroll
    for (int off = 16; off; off >>= 1) s += __shfl_xor_sync(0xffffffffu, s, off);
    __shared__ float ws[8];
    int lane = threadIdx.x & 31, w = threadIdx.x >> 5;
    if (lane == 0) ws[w] = s;
    __syncthreads();
    if (threadIdx.x == 0) {
        float t = 0.f;
        #pragma unroll
        for (int k = 0; k < 8; k++) t += ws[k];
        g_norm[blockIdx.x] = t;
    }
}

// tp[p,i] = sum_j omega[c,i,j] * w[p,j]; split-K x4 via atomicAdd
__global__ __launch_bounds__(256) void tp_kernel(const float* __restrict__ omega,
                                                 const float* __restrict__ protos) {
    int c = blockIdx.y;
    int i0 = blockIdx.x * 32;
    int ks = blockIdx.z;
    int tid = threadIdx.x;
    int tx = tid & 31;
    int ty = tid >> 5;
    __shared__ float w_s[32][33];
    __shared__ float om_s[32][33];
    float acc[4] = {0.f, 0.f, 0.f, 0.f};
    for (int t = 0; t < 4; t++) {
        int j0 = ks * 128 + t * 32;
        #pragma unroll
        for (int l = 0; l < 4; l++) {
            int s = tid + l * 256;
            int r = s >> 5, jj = s & 31;
            w_s[r][jj]  = protos[(r * 8 + c) * D_ + j0 + jj];
            om_s[r][jj] = omega[((size_t)c * D_ + i0 + r) * D_ + j0 + jj];
        }
        __syncthreads();
        #pragma unroll
        for (int jj = 0; jj < 32; jj++) {
            float wv = w_s[tx][jj];
            #pragma unroll
            for (int r = 0; r < 4; r++)
                acc[r] += om_s[ty * 4 + r][jj] * wv;
        }
        __syncthreads();
    }
    #pragma unroll
    for (int r = 0; r < 4; r++)
        atomicAdd(&g_tp[(tx * 8 + c) * D_ + i0 + ty * 4 + r], acc[r]);
}

// u[p,j] = sum_i tp[p,i] * omega[c,i,j]; split-K x4 via atomicAdd
__global__ __launch_bounds__(256) void u_kernel(const float* __restrict__ omega) {
    int c = blockIdx.y, j0 = blockIdx.x * 32;
    int ks = blockIdx.z;
    int tid = threadIdx.x;
    int jx = tid & 7;
    int py = tid >> 3;
    __shared__ float tp_s[32][33];
    __shared__ float om_s[32][32];
    float ax = 0.f, ay = 0.f, az = 0.f, aw = 0.f;
    for (int t = 0; t < 4; t++) {
        int i0 = ks * 128 + t * 32;
        #pragma unroll
        for (int l = 0; l < 4; l++) {
            int s = tid + l * 256;
            int p = s >> 5, ii = s & 31;
            tp_s[p][ii] = g_tp[(p * 8 + c) * D_ + i0 + ii];
        }
        #pragma unroll
        for (int l = 0; l < 4; l++) {
            int s = tid + l * 256;
            int ii = s >> 5, jj = s & 31;
            om_s[ii][jj] = omega[((size_t)c * D_ + i0 + ii) * D_ + j0 + jj];
        }
        __syncthreads();
        #pragma unroll
        for (int ii = 0; ii < 32; ii++) {
            float tv = tp_s[py][ii];
            float4 ov = *(const float4*)&om_s[ii][jx * 4];
            ax += tv * ov.x; ay += tv * ov.y; az += tv * ov.z; aw += tv * ov.w;
        }
        __syncthreads();
    }
    float* dst = &g_u[(size_t)(py * 8 + c) * D_ + j0 + jx * 4];
    atomicAdd(dst + 0, ax);
    atomicAdd(dst + 1, ay);
    atomicAdd(dst + 2, az);
    atomicAdd(dst + 3, aw);
}

__global__ void p2_kernel() {
    int p = blockIdx.x;
    int tid = threadIdx.x;
    float s = 0.f;
    for (int i = tid; i < D_; i += 128) {
        float v = g_tp[p * D_ + i];
        s += v * v;
    }
    #pragma unroll
    for (int off = 16; off; off >>= 1) s += __shfl_xor_sync(0xffffffffu, s, off);
    __shared__ float ws[4];
    if ((tid & 31) == 0) ws[tid >> 5] = s;
    __syncthreads();
    if (tid == 0) g_p2[p] = ws[0] + ws[1] + ws[2] + ws[3];
}

// ================= x2 via mma.sync bf16 + ldmatrix =========================
// CTA 128m x 128n x K=512 (BK=64), 4 warps (2m x 2n), warp tile 64x64
// (MMA/LDSM ratio 4.0 vs 2.67 at 64x32), 3-stage cp.async pipeline.
// Epilogue: rowwise sumsq, cross-warp_n smem reduce, coalesced store.
__global__ __launch_bounds__(128) void x2_mma_kernel() {
    extern __shared__ char sm[];
    __shared__ float red[2][128];   // [warp_n][local row]
    const int tid = threadIdx.x, lane = tid & 31, wid = tid >> 5;  // 4 warps
    const int warp_m = wid & 1, warp_n = wid >> 1;
    const int b0 = blockIdx.x * 128, ny = blockIdx.y, c = blockIdx.z;
    const int n0 = ny * 128;
    const int r4 = lane >> 2, kq4 = lane & 3;

    const __nv_bfloat16* Asrc = g_xb + (size_t)b0 * D_;
    const __nv_bfloat16* Bsrc = g_omb + (size_t)c * D_ * D_ + (size_t)n0 * D_;
    uint32_t smB = smem_u32(sm);

    float acc[4][8][4];
    #pragma unroll
    for (int i = 0; i < 4; i++)
        #pragma unroll
        for (int j = 0; j < 8; j++)
            #pragma unroll
            for (int q = 0; q < 4; q++) acc[i][j][q] = 0.f;

    uint32_t aBase[4], aX[4];
    const int aRowL = lane & 15, aHalf = (lane >> 4) * 16;
    #pragma unroll
    for (int mt = 0; mt < 4; mt++) {
        int r = warp_m * 64 + mt * 16 + aRowL;
        aBase[mt] = r * 128; aX[mt] = (r & 7) << 4;
    }
    uint32_t bBase[4], bX[4];
    const int bRowL = ((lane >> 4) << 3) | (lane & 7);
    const int bHalf = ((lane >> 3) & 1) * 16;
    #pragma unroll
    for (int np = 0; np < 4; np++) {
        int r = warp_n * 64 + np * 16 + bRowL;
        bBase[np] = 16384 + r * 128; bX[np] = (r & 7) << 4;
    }

    // stage = 32KB: A 128x64 bf16 (16KB) + B 128x64 bf16 (16KB); 128 threads
    auto load_stage = [&](int buf, int k0) {
        uint32_t aB = smB + buf * 32768;
        uint32_t bB = aB + 16384;
        #pragma unroll
        for (int l = 0; l < 8; l++) {
            int idx = tid + l * 128;
            int m = idx >> 3, kq = idx & 7;
            uint32_t byteo = m * 128 + kq * 16;
            CP_ASYNC16(aB + SW(byteo), Asrc + (size_t)m * D_ + k0 + kq * 8);
        }
        #pragma unroll
        for (int l = 0; l < 8; l++) {
            int idx = tid + l * 128;
            int n = idx >> 3, kq = idx & 7;
            uint32_t byteo = n * 128 + kq * 16;
            CP_ASYNC16(bB + SW(byteo), Bsrc + (size_t)n * D_ + k0 + kq * 8);
        }
        CP_COMMIT();
    };

    load_stage(0, 0);
    load_stage(1, 64);
    for (int it = 0; it < 8; it++) {
        if (it == 7) CP_WAIT(0); else CP_WAIT(1);
        __syncthreads();
        if (it + 2 < 8) load_stage((it + 2) % 3, (it + 2) * 64);
        uint32_t stage = smB + (uint32_t)(it % 3) * 32768;
        #pragma unroll
        for (int ks = 0; ks < 4; ks++) {
            uint32_t kb = ks * 32;
            uint32_t a[4][4], b[4][4];
            #pragma unroll
            for (int mt = 0; mt < 4; mt++)
                LDSM_X4(a[mt], stage + aBase[mt] + ((kb + aHalf) ^ aX[mt]));
            #pragma unroll
            for (int np = 0; np < 4; np++)
                LDSM_X4(b[np], stage + bBase[np] + ((kb + bHalf) ^ bX[np]));
            #pragma unroll
            for (int mt = 0; mt < 4; mt++)
                #pragma unroll
                for (int nt = 0; nt < 8; nt++)
                    MMA_BF16(acc[mt][nt], a[mt], (&b[nt >> 1][(nt & 1) * 2]));
        }
    }

    // epilogue: per-warp rowwise sumsq partials (64 n-cols each) ->
    // smem reduce across the 2 warp_n groups -> one store per row.
    #pragma unroll
    for (int mt = 0; mt < 4; mt++) {
        float s0 = 0.f, s8 = 0.f;
        #pragma unroll
        for (int nt = 0; nt < 8; nt++) {
            s0 += acc[mt][nt][0] * acc[mt][nt][0] + acc[mt][nt][1] * acc[mt][nt][1];
            s8 += acc[mt][nt][2] * acc[mt][nt][2] + acc[mt][nt][3] * acc[mt][nt][3];
        }
        s0 += __shfl_xor_sync(0xffffffffu, s0, 1);
        s0 += __shfl_xor_sync(0xffffffffu, s0, 2);
        s8 += __shfl_xor_sync(0xffffffffu, s8, 1);
        s8 += __shfl_xor_sync(0xffffffffu, s8, 2);
        if (kq4 == 0) {
            int rl = warp_m * 64 + mt * 16 + r4;
            red[warp_n][rl]     = s0;
            red[warp_n][rl + 8] = s8;
        }
    }
    __syncthreads();
    g_x2p[ny][c][b0 + tid] = red[0][tid] + red[1][tid];
}

// ============== dist via mma.sync bf16 + ldmatrix, fused epilogue ==========
// CTA 32m x 256n x 512 (BK=64), 8 warps (2m x 4n), warp tile 16x64.
// Last CTA (atomic counter) also performs the final loss reduction.
__global__ __launch_bounds__(256) void dist_mma_kernel(const int* __restrict__ y,
                                                       const int* __restrict__ labels,
                                                       float* __restrict__ out) {
    extern __shared__ char sm[];
    __shared__ float x2s[C_][32];
    __shared__ float p2_s[P_];
    __shared__ int   lab_s[P_];
    __shared__ int   ys_s[32];
    __shared__ float pos_s[4][32];
    __shared__ float neg_s[4][32];
    __shared__ bool  isLast;

    const int tid = threadIdx.x, lane = tid & 31, wid = tid >> 5;
    const int warp_m = wid & 1, warp_n = wid >> 1;
    const int b0 = blockIdx.x * 32;
    const int r4 = lane >> 2, kq4 = lane & 3;

    const __nv_bfloat16* Asrc = g_xb + (size_t)b0 * D_;
    uint32_t smB = smem_u32(sm);

    for (int i = tid; i < P_; i += 256) {
        p2_s[i]  = g_p2[i];
        lab_s[i] = labels[i];
    }
    if (tid < C_ * 32) {
        int c = tid >> 5, r = tid & 31;
        x2s[c][r] = g_x2p[0][c][b0 + r] + g_x2p[1][c][b0 + r]
                  + g_x2p[2][c][b0 + r] + g_x2p[3][c][b0 + r];
    }
    if (tid < 32) ys_s[tid] = y[b0 + tid];

    float acc[8][4];
    #pragma unroll
    for (int j = 0; j < 8; j++)
        #pragma unroll
        for (int q = 0; q < 4; q++) acc[j][q] = 0.f;

    uint32_t aBase, aX;
    const int aRowL = lane & 15, aHalf = (lane >> 4) * 16;
    {
        int r = warp_m * 16 + aRowL;
        aBase = r * 128; aX = (r & 7) << 4;
    }
    uint32_t bBase[4], bX[4];
    const int bRowL = ((lane >> 4) << 3) | (lane & 7);
    const int bHalf = ((lane >> 3) & 1) * 16;
    #pragma unroll
    for (int np = 0; np < 4; np++) {
        int r = warp_n * 64 + np * 16 + bRowL;
        bBase[np] = 4096 + r * 128; bX[np] = (r & 7) << 4;
    }

    // stage = 36KB: A 32x64 bf16 (4KB) + B 256x64 bf16 (32KB)
    auto load_stage = [&](int buf, int k0) {
        uint32_t aB = smB + buf * 36864;
        uint32_t bB = aB + 4096;
        {
            int m = tid >> 3, kq = tid & 7;
            uint32_t byteo = m * 128 + kq * 16;
            CP_ASYNC16(aB + SW(byteo), Asrc + (size_t)m * D_ + k0 + kq * 8);
        }
        #pragma unroll
        for (int l = 0; l < 8; l++) {
            int idx = tid + l * 256;
            int n = idx >> 3, kq = idx & 7;
            uint32_t byteo = n * 128 + kq * 16;
            CP_ASYNC16(bB + SW(byteo), g_ub + (size_t)n * D_ + k0 + kq * 8);
        }
        CP_COMMIT();
    };

    load_stage(0, 0);
    load_stage(1, 64);
    for (int it = 0; it < 8; it++) {
        if (it == 7) CP_WAIT(0); else CP_WAIT(1);
        __syncthreads();
        if (it + 2 < 8) load_stage((it + 2) % 3, (it + 2) * 64);
        uint32_t stage = smB + (uint32_t)(it % 3) * 36864;
        #pragma unroll
        for (int ks = 0; ks < 4; ks++) {
            uint32_t kb = ks * 32;
            uint32_t a[4], b[4][4];
            LDSM_X4(a, stage + aBase + ((kb + aHalf) ^ aX));
            #pragma unroll
            for (int np = 0; np < 4; np++)
                LDSM_X4(b[np], stage + bBase[np] + ((kb + bHalf) ^ bX[np]));
            #pragma unroll
            for (int nt = 0; nt < 8; nt++)
                MMA_BF16(acc[nt], a, (&b[nt >> 1][(nt & 1) * 2]));
        }
    }

    // ---- fused epilogue ----
    {
        int rl = warp_m * 16 + r4;
        int y0 = ys_s[rl], y8 = ys_s[rl + 8];
        float p0 = INFINITY, n0v = INFINITY, p8 = INFINITY, n8v = INFINITY;
        #pragma unroll
        for (int nt = 0; nt < 8; nt++) {
            #pragma unroll
            for (int q = 0; q < 2; q++) {
                int p = warp_n * 64 + nt * 8 + kq4 * 2 + q;
                int lb = lab_s[p];
                float pp = p2_s[p];
                float d0 = x2s[lb][rl]     + pp - 2.0f * acc[nt][q];
                float d8 = x2s[lb][rl + 8] + pp - 2.0f * acc[nt][2 + q];
                if (lb == y0) p0 = fminf(p0, d0); else n0v = fminf(n0v, d0);
                if (lb == y8) p8 = fminf(p8, d8); else n8v = fminf(n8v, d8);
            }
        }
        #pragma unroll
        for (int off = 1; off < 4; off <<= 1) {
            p0  = fminf(p0,  __shfl_xor_sync(0xffffffffu, p0,  off));
            n0v = fminf(n0v, __shfl_xor_sync(0xffffffffu, n0v, off));
            p8  = fminf(p8,  __shfl_xor_sync(0xffffffffu, p8,  off));
            n8v = fminf(n8v, __shfl_xor_sync(0xffffffffu, n8v, off));
        }
        if (kq4 == 0) {
            pos_s[warp_n][rl]     = p0;  neg_s[warp_n][rl]     = n0v;
            pos_s[warp_n][rl + 8] = p8;  neg_s[warp_n][rl + 8] = n8v;
        }
    }
    __syncthreads();
    if (tid < 32) {
        float pos = fminf(fminf(pos_s[0][tid], pos_s[1][tid]),
                          fminf(pos_s[2][tid], pos_s[3][tid]));
        float neg = fminf(fminf(neg_s[0][tid], neg_s[1][tid]),
                          fminf(neg_s[2][tid], neg_s[3][tid]));
        float mu = (pos - neg) / (pos + neg);
        float sg = 1.0f / (1.0f + expf(-mu));
        #pragma unroll
        for (int off = 16; off; off >>= 1) sg += __shfl_xor_sync(0xffffffffu, sg, off);
        if (tid == 0) g_sg[blockIdx.x] = sg;
    }

    // ---- last-CTA final reduction ----
    __threadfence();
    if (tid == 0) isLast = (atomicAdd(&g_ctr, 1u) == (unsigned)(B_ / 32 - 1));
    __syncthreads();
    if (isLast) {
        float sg = 0.f, nm = 0.f;
        if (tid < B_ / 32) sg = g_sg[tid];
        #pragma unroll
        for (int k = 0; k < 8; k++) nm += g_norm[tid + k * 256];
        #pragma unroll
        for (int off = 16; off; off >>= 1) {
            sg += __shfl_xor_sync(0xffffffffu, sg, off);
            nm += __shfl_xor_sync(0xffffffffu, nm, off);
        }
        __shared__ float ss[8], sn[8];
        if (lane == 0) { ss[wid] = sg; sn[wid] = nm; }
        __syncthreads();
        if (tid == 0) {
            float a = 0.f, b = 0.f;
            #pragma unroll
            for (int k = 0; k < 8; k++) { a += ss[k]; b += sn[k]; }
            out[0] = a * (1.0f / (float)B_) + 0.01f * sqrtf(b);
        }
    }
}

// ===========================================================================
extern "C" void kernel_launch(void* const* d_in, const int* in_sizes, int n_in,
                              void* d_out, int out_size) {
    const float* x      = (const float*)d_in[0];
    const int*   y      = (const int*)d_in[1];
    const float* protos = (const float*)d_in[2];
    const float* omega  = (const float*)d_in[3];
    const int*   labels = (const int*)d_in[4];
    float* out = (float*)d_out;

    static cudaStream_t s2 = nullptr;
    static cudaEvent_t evA = nullptr, evB = nullptr;
    static __nv_bfloat16* p_xb = nullptr;
    static __nv_bfloat16* p_ub = nullptr;
    static float* p_u = nullptr;
    if (s2 == nullptr) {                 // first (uncaptured) call only
        cudaStreamCreateWithFlags(&s2, cudaStreamNonBlocking);
        cudaEventCreateWithFlags(&evA, cudaEventDisableTiming);
        cudaEventCreateWithFlags(&evB, cudaEventDisableTiming);
        cudaFuncSetAttribute(x2_mma_kernel,
                             cudaFuncAttributeMaxDynamicSharedMemorySize, 98304);
        cudaFuncSetAttribute(dist_mma_kernel,
                             cudaFuncAttributeMaxDynamicSharedMemorySize, 110592);
        cudaGetSymbolAddress((void**)&p_xb,  g_xb);
        cudaGetSymbolAddress((void**)&p_ub,  g_ub);
        cudaGetSymbolAddress((void**)&p_u,   g_u);
    }

    cudaEventRecord(evA, 0);
    cudaStreamWaitEvent(s2, evA, 0);

    // main stream (R7 topology): both converts, then x2 directly — no
    // cross-stream event in front of the big GEMM.
    f2bf_kernel<<<(B_ * D_ / 4 + 255) / 256, 256>>>(x, p_xb, B_ * D_ / 4);
    convom_kernel<<<C_ * D_ * D_ / 4 / 256, 256>>>(omega);
    x2_mma_kernel<<<dim3(B_ / 128, 4, C_), 128, 98304>>>();

    // side stream: prototype chain (independent of x2)
    zero_side_kernel<<<(P_ * D_ + 255) / 256, 256, 0, s2>>>();
    tp_kernel<<<dim3(D_ / 32, C_, 4), 256, 0, s2>>>(omega, protos);
    p2_kernel<<<P_, 128, 0, s2>>>();
    u_kernel<<<dim3(D_ / 32, C_, 4), 256, 0, s2>>>(omega);
    f2bf_kernel<<<(P_ * D_ / 4 + 255) / 256, 256, 0, s2>>>(p_u, p_ub, P_ * D_ / 4);
    cudaEventRecord(evB, s2);          // everything dist needs is ready

    cudaStreamWaitEvent(0, evB, 0);
    dist_mma_kernel<<<B_ / 32, 256, 110592>>>(y, labels, out);
}